// round 6
// baseline (speedup 1.0000x reference)
#include <cuda_runtime.h>
#include <math.h>

#define MAX_B    8192
#define NBUCK    4096
#define BSCALE   128.0f       // bucket = int(loss * 128), covers [0, 32)
#define LIST_CAP 1024
#define SORT_CAP 128
#define NT       320
#define BPT      13           // ceil(NBUCK / NT)

__device__ float g_loss[MAX_B];
__device__ int   g_hcnt[NBUCK];    // zero-invariant across calls
__device__ float g_hsum[NBUCK];    // zero-invariant across calls
__device__ int   g_nneg;           // zero-invariant across calls
__device__ float g_tot;            // zero-invariant across calls
__device__ int   g_ticket;         // zero-invariant across calls

// ---------------------------------------------------------------------------
// Single fused kernel. One block (320 threads) per row:
//   Phase A (all blocks): branchless single-pass top-2 + sum(exp(x)),
//     epilogue deposits loss, histogram (count,sum), nneg, total via
//     spread global atomics, then __threadfence + ticket.
//   Phase B (chip-wide last block only): histogram prefix-scan selection
//     of the sorted-prefix boundary (mask is provably a prefix), exact
//     boundary walk on the crossing bucket, scalar output, scratch re-zero.
// ---------------------------------------------------------------------------
__global__ __launch_bounds__(NT) void npc_fused_kernel(
    const float* __restrict__ logits,
    const int*   __restrict__ target,
    float* __restrict__ out,
    int C, int B)
{
    const int row = blockIdx.x;
    const float* __restrict__ p = logits + (long long)row * (long long)C;
    const int tid  = threadIdx.x;
    const int warp = tid >> 5;
    const int lane = tid & 31;

    // ===================== Phase A: per-row pass =====================
    float m1 = -INFINITY;
    float m2 = -INFINITY;
    float s  = 0.0f;

    const int C4 = C >> 2;                      // 8000; 8000/320 = 25 exact
    const float4* __restrict__ p4 = (const float4*)p;
#pragma unroll 5
    for (int i = tid; i < C4; i += NT) {
        float4 v = p4[i];
        float xs[4] = {v.x, v.y, v.z, v.w};
#pragma unroll
        for (int e = 0; e < 4; e++) {
            float x  = xs[e];
            float hi = fmaxf(m1, x);
            float lo = fminf(m1, x);
            m2 = fmaxf(m2, lo);
            m1 = hi;
            s += __expf(x);
        }
    }
    for (int i = (C4 << 2) + tid; i < C; i += NT) {   // tail safety
        float x  = p[i];
        float hi = fmaxf(m1, x);
        float lo = fminf(m1, x);
        m2 = fmaxf(m2, lo);
        m1 = hi;
        s += __expf(x);
    }

#pragma unroll
    for (int o = 16; o > 0; o >>= 1) {
        float om1 = __shfl_xor_sync(0xffffffffu, m1, o);
        float om2 = __shfl_xor_sync(0xffffffffu, m2, o);
        float os  = __shfl_xor_sync(0xffffffffu, s,  o);
        float lo  = fminf(m1, om1);
        m1 = fmaxf(m1, om1);
        m2 = fmaxf(lo, fmaxf(m2, om2));
        s += os;
    }

    __shared__ float sm1[10], sm2[10], ss[10];
    __shared__ int   s_last;
    if (lane == 0) { sm1[warp] = m1; sm2[warp] = m2; ss[warp] = s; }
    __syncthreads();

    if (tid == 0) {
        float M1 = sm1[0], M2 = sm2[0], S = ss[0];
        for (int w = 1; w < (NT >> 5); w++) {
            float om1 = sm1[w];
            float lo  = fminf(M1, om1);
            M1 = fmaxf(M1, om1);
            M2 = fmaxf(lo, fmaxf(M2, sm2[w]));
            S += ss[w];
        }
        float tgt = p[target[row]];
        float lse = __logf(S);

        float margin1 = tgt - M1;
        float margin  = (margin1 != 0.0f) ? margin1 : (tgt - M2);
        float lv = (margin >= 0.0f) ? fmaxf(1.0f - margin, 0.0f)
                                    : fmaxf(1.0f - tgt + lse, 0.0f);
        g_loss[row] = lv;

        int b = (int)(lv * BSCALE);
        b = max(0, min(NBUCK - 1, b));
        atomicAdd(&g_hcnt[b], 1);
        atomicAdd(&g_hsum[b], lv);
        if (margin < 0.0f) atomicAdd(&g_nneg, 1);
        atomicAdd(&g_tot, lv);

        __threadfence();
        int t = atomicAdd(&g_ticket, 1);
        s_last = (t == gridDim.x - 1) ? 1 : 0;
    }
    __syncthreads();
    if (!s_last) return;

    // ============ Phase B: last block runs the finalize ============
    __threadfence();   // acquire side of the ticket handshake

    __shared__ int   wtc[10];
    __shared__ float wts[10];
    __shared__ float list[LIST_CAP];
    __shared__ int   s_bstar, s_k0cnt, s_cntb, s_ln;
    __shared__ float s_S0, s_sumb;

    if (tid == 0) { s_bstar = -1; s_ln = 0; }

    const int   nneg      = g_nneg;
    const float total_sum = g_tot;
    const float threshold = 0.81f * (float)B + 0.9f * (float)nneg;
    const float T2        = threshold + 2.0f;
    const bool  all_sel   = ((float)B + total_sum <= T2);

    // ---- load histogram: BPT buckets/thread; serial totals ----
    const int b0 = tid * BPT;
    int   hc[BPT];
    float hs[BPT];
    int   ci = 0;
    float si = 0.0f;
#pragma unroll
    for (int j = 0; j < BPT; j++) {
        int b = b0 + j;
        int   c = (b < NBUCK) ? g_hcnt[b] : 0;
        float f = (b < NBUCK) ? g_hsum[b] : 0.0f;
        hc[j] = c; hs[j] = f;
        ci += c;  si += f;
    }

    // ---- hierarchical exclusive pair-scan over thread totals ----
    int   wc = ci;
    float ws = si;
#pragma unroll
    for (int o = 1; o < 32; o <<= 1) {
        int   tc = __shfl_up_sync(0xffffffffu, wc, o);
        float ts = __shfl_up_sync(0xffffffffu, ws, o);
        if (lane >= o) { wc += tc; ws += ts; }
    }
    if (lane == 31) { wtc[warp] = wc; wts[warp] = ws; }
    __syncthreads();
    if (warp == 0) {
        int   tc = (lane < 10) ? wtc[lane] : 0;
        float ts = (lane < 10) ? wts[lane] : 0.0f;
        int   c2 = tc;
        float s2 = ts;
#pragma unroll
        for (int o = 1; o < 32; o <<= 1) {
            int   uc = __shfl_up_sync(0xffffffffu, c2, o);
            float us = __shfl_up_sync(0xffffffffu, s2, o);
            if (lane >= o) { c2 += uc; s2 += us; }
        }
        if (lane < 10) { wtc[lane] = c2 - tc; wts[lane] = s2 - ts; }
    }
    __syncthreads();
    int   K = wtc[warp] + (wc - ci);    // exclusive prefix before this thread
    float S = wts[warp] + (ws - si);

    // ---- locate the unique crossing bucket ----
    if (!all_sel) {
#pragma unroll
        for (int j = 0; j < BPT; j++) {
            float before = (float)K + S;
            float after  = (float)(K + hc[j]) + (S + hs[j]);
            if (before <= T2 && after > T2) {
                s_bstar  = b0 + j;
                s_k0cnt  = K;
                s_S0     = S;
                s_cntb   = hc[j];
                s_sumb   = hs[j];
            }
            K += hc[j];
            S += hs[j];
        }
    }
    __syncthreads();

    // ---- gather crossing bucket members from g_loss (L2-hot) ----
    const int bstar = s_bstar;
    if (bstar >= 0) {
        for (int i = tid; i < B; i += NT) {
            float L = g_loss[i];
            int b = (int)(L * BSCALE);
            b = max(0, min(NBUCK - 1, b));
            if (b == bstar) {
                int idx = atomicAdd(&s_ln, 1);
                if (idx < LIST_CAP) list[idx] = L;
            }
        }
    }
    __syncthreads();

    // ---- exact boundary walk (thread 0) ----
    if (tid == 0) {
        float Sf, cntf;
        if (all_sel || bstar < 0) {
            Sf = total_sum; cntf = (float)B;
        } else {
            int n = s_ln;
            if (n <= SORT_CAP && n <= LIST_CAP) {
                for (int a = 1; a < n; a++) {           // insertion sort asc
                    float x = list[a];
                    int bp = a - 1;
                    while (bp >= 0 && list[bp] > x) { list[bp + 1] = list[bp]; bp--; }
                    list[bp + 1] = x;
                }
                int   k  = s_k0cnt;
                float Sa = s_S0;
                for (int t = 0; t < n; t++) {
                    float val = list[t];
                    if (Sa + val + (float)(k + 1) <= T2) { Sa += val; k++; }
                    else break;
                }
                Sf = Sa; cntf = (float)k;
            } else {
                float avg = s_sumb / (float)s_cntb;     // near-equal fallback
                float j = floorf((T2 - s_S0 - (float)s_k0cnt) / (avg + 1.0f));
                j = fmaxf(j, 0.0f);
                j = fminf(j, (float)s_cntb);
                Sf   = s_S0 + j * avg;
                cntf = (float)s_k0cnt + j;
            }
        }
        float np2 = threshold - cntf;
        out[0] = fmaxf(Sf, np2) / cntf;
    }

    // ---- restore scratch to zero for the next call ----
    __syncthreads();
#pragma unroll
    for (int j = 0; j < BPT; j++) {
        int b = b0 + j;
        if (b < NBUCK) { g_hcnt[b] = 0; g_hsum[b] = 0.0f; }
    }
    if (tid == 0) { g_nneg = 0; g_tot = 0.0f; g_ticket = 0; }
}

// ---------------------------------------------------------------------------
extern "C" void kernel_launch(void* const* d_in, const int* in_sizes, int n_in,
                              void* d_out, int out_size)
{
    const float* logits = (const float*)d_in[0];
    const int*   target = (const int*)d_in[1];
    const int B = in_sizes[1];
    const int C = in_sizes[0] / B;

    npc_fused_kernel<<<B, NT>>>(logits, target, (float*)d_out, C, B);
}

// round 7
// speedup vs baseline: 1.0399x; 1.0399x over previous
#include <cuda_runtime.h>
#include <math.h>

#define MAX_B    8192
#define NBUCK    4096
#define BSCALE   128.0f       // bucket = int(loss * 128), covers [0, 32)
#define LIST_CAP 1024
#define SORT_CAP 128
#define NT       320
#define BPT      13           // ceil(NBUCK / NT)

__device__ float g_loss[MAX_B];
__device__ int   g_hcnt[NBUCK];    // zero-invariant across calls
__device__ float g_hsum[NBUCK];    // zero-invariant across calls
__device__ int   g_nneg;           // zero-invariant across calls
__device__ float g_tot;            // zero-invariant across calls
__device__ int   g_ticket;         // zero-invariant across calls

// ---------------------------------------------------------------------------
// Single fused kernel, register-capped so Phase A keeps 5 blocks/SM.
//   Phase A (all blocks): branchless single-pass top-2 + sum(exp(x)),
//     epilogue deposits loss, histogram (count,sum), nneg, total via
//     spread global atomics, then __threadfence + ticket.
//   Phase B (chip-wide last block): register-light histogram walk —
//     totals+scan pass, then an L2 re-read pass to locate the crossing
//     bucket; exact boundary walk; scalar out; scratch re-zero.
// ---------------------------------------------------------------------------
__global__ void __launch_bounds__(NT, 5) npc_fused_kernel(
    const float* __restrict__ logits,
    const int*   __restrict__ target,
    float* __restrict__ out,
    int C, int B)
{
    const int row = blockIdx.x;
    const float* __restrict__ p = logits + (long long)row * (long long)C;
    const int tid  = threadIdx.x;
    const int warp = tid >> 5;
    const int lane = tid & 31;

    // ===================== Phase A: per-row pass =====================
    float m1 = -INFINITY;
    float m2 = -INFINITY;
    float s  = 0.0f;

    const int C4 = C >> 2;                      // 8000; 8000/320 = 25 exact
    const float4* __restrict__ p4 = (const float4*)p;
#pragma unroll 5
    for (int i = tid; i < C4; i += NT) {
        float4 v = p4[i];
        float xs[4] = {v.x, v.y, v.z, v.w};
#pragma unroll
        for (int e = 0; e < 4; e++) {
            float x  = xs[e];
            float hi = fmaxf(m1, x);
            float lo = fminf(m1, x);
            m2 = fmaxf(m2, lo);
            m1 = hi;
            s += __expf(x);
        }
    }
    for (int i = (C4 << 2) + tid; i < C; i += NT) {   // tail safety
        float x  = p[i];
        float hi = fmaxf(m1, x);
        float lo = fminf(m1, x);
        m2 = fmaxf(m2, lo);
        m1 = hi;
        s += __expf(x);
    }

#pragma unroll
    for (int o = 16; o > 0; o >>= 1) {
        float om1 = __shfl_xor_sync(0xffffffffu, m1, o);
        float om2 = __shfl_xor_sync(0xffffffffu, m2, o);
        float os  = __shfl_xor_sync(0xffffffffu, s,  o);
        float lo  = fminf(m1, om1);
        m1 = fmaxf(m1, om1);
        m2 = fmaxf(lo, fmaxf(m2, om2));
        s += os;
    }

    __shared__ float sm1[10], sm2[10], ss[10];
    __shared__ int   s_last;
    if (lane == 0) { sm1[warp] = m1; sm2[warp] = m2; ss[warp] = s; }
    __syncthreads();

    if (tid == 0) {
        float M1 = sm1[0], M2 = sm2[0], S = ss[0];
        for (int w = 1; w < (NT >> 5); w++) {
            float om1 = sm1[w];
            float lo  = fminf(M1, om1);
            M1 = fmaxf(M1, om1);
            M2 = fmaxf(lo, fmaxf(M2, sm2[w]));
            S += ss[w];
        }
        float tgt = p[target[row]];
        float lse = __logf(S);

        float margin1 = tgt - M1;
        float margin  = (margin1 != 0.0f) ? margin1 : (tgt - M2);
        float lv = (margin >= 0.0f) ? fmaxf(1.0f - margin, 0.0f)
                                    : fmaxf(1.0f - tgt + lse, 0.0f);
        g_loss[row] = lv;

        int b = (int)(lv * BSCALE);
        b = max(0, min(NBUCK - 1, b));
        atomicAdd(&g_hcnt[b], 1);
        atomicAdd(&g_hsum[b], lv);
        if (margin < 0.0f) atomicAdd(&g_nneg, 1);
        atomicAdd(&g_tot, lv);

        __threadfence();
        int t = atomicAdd(&g_ticket, 1);
        s_last = (t == gridDim.x - 1) ? 1 : 0;
    }
    __syncthreads();
    if (!s_last) return;

    // ============ Phase B: last block runs the finalize ============
    __threadfence();   // acquire side of the ticket handshake

    __shared__ int   wtc[10];
    __shared__ float wts[10];
    __shared__ float list[LIST_CAP];
    __shared__ int   s_bstar, s_k0cnt, s_cntb, s_ln;
    __shared__ float s_S0, s_sumb;

    if (tid == 0) { s_bstar = -1; s_ln = 0; }

    const int   nneg      = g_nneg;
    const float total_sum = g_tot;
    const float threshold = 0.81f * (float)B + 0.9f * (float)nneg;
    const float T2        = threshold + 2.0f;
    const bool  all_sel   = ((float)B + total_sum <= T2);

    // ---- pass 1: per-thread bucket totals (no register arrays) ----
    const int b0 = tid * BPT;
    int   ci = 0;
    float si = 0.0f;
    for (int j = 0; j < BPT; j++) {
        int b = b0 + j;
        if (b < NBUCK) { ci += g_hcnt[b]; si += g_hsum[b]; }
    }

    // ---- hierarchical exclusive pair-scan over thread totals ----
    int   wc = ci;
    float ws = si;
#pragma unroll
    for (int o = 1; o < 32; o <<= 1) {
        int   tc = __shfl_up_sync(0xffffffffu, wc, o);
        float ts = __shfl_up_sync(0xffffffffu, ws, o);
        if (lane >= o) { wc += tc; ws += ts; }
    }
    if (lane == 31) { wtc[warp] = wc; wts[warp] = ws; }
    __syncthreads();
    if (warp == 0) {
        int   tc = (lane < 10) ? wtc[lane] : 0;
        float ts = (lane < 10) ? wts[lane] : 0.0f;
        int   c2 = tc;
        float s2 = ts;
#pragma unroll
        for (int o = 1; o < 32; o <<= 1) {
            int   uc = __shfl_up_sync(0xffffffffu, c2, o);
            float us = __shfl_up_sync(0xffffffffu, s2, o);
            if (lane >= o) { c2 += uc; s2 += us; }
        }
        if (lane < 10) { wtc[lane] = c2 - tc; wts[lane] = s2 - ts; }
    }
    __syncthreads();
    int   K = wtc[warp] + (wc - ci);    // exclusive prefix before this thread
    float S = wts[warp] + (ws - si);

    // ---- pass 2: re-read buckets from L2, locate crossing bucket ----
    if (!all_sel) {
        for (int j = 0; j < BPT; j++) {
            int b = b0 + j;
            if (b < NBUCK) {
                int   c = g_hcnt[b];
                float f = g_hsum[b];
                float before = (float)K + S;
                float after  = (float)(K + c) + (S + f);
                if (before <= T2 && after > T2) {
                    s_bstar = b;
                    s_k0cnt = K;
                    s_S0    = S;
                    s_cntb  = c;
                    s_sumb  = f;
                }
                K += c;
                S += f;
            }
        }
    }
    __syncthreads();

    // ---- gather crossing bucket members from g_loss (L2-hot) ----
    const int bstar = s_bstar;
    if (bstar >= 0) {
        for (int i = tid; i < B; i += NT) {
            float L = g_loss[i];
            int b = (int)(L * BSCALE);
            b = max(0, min(NBUCK - 1, b));
            if (b == bstar) {
                int idx = atomicAdd(&s_ln, 1);
                if (idx < LIST_CAP) list[idx] = L;
            }
        }
    }
    __syncthreads();

    // ---- exact boundary walk (thread 0) ----
    if (tid == 0) {
        float Sf, cntf;
        if (all_sel || bstar < 0) {
            Sf = total_sum; cntf = (float)B;
        } else {
            int n = s_ln;
            if (n <= SORT_CAP && n <= LIST_CAP) {
                for (int a = 1; a < n; a++) {           // insertion sort asc
                    float x = list[a];
                    int bp = a - 1;
                    while (bp >= 0 && list[bp] > x) { list[bp + 1] = list[bp]; bp--; }
                    list[bp + 1] = x;
                }
                int   k  = s_k0cnt;
                float Sa = s_S0;
                for (int t = 0; t < n; t++) {
                    float val = list[t];
                    if (Sa + val + (float)(k + 1) <= T2) { Sa += val; k++; }
                    else break;
                }
                Sf = Sa; cntf = (float)k;
            } else {
                float avg = s_sumb / (float)s_cntb;     // near-equal fallback
                float j = floorf((T2 - s_S0 - (float)s_k0cnt) / (avg + 1.0f));
                j = fmaxf(j, 0.0f);
                j = fminf(j, (float)s_cntb);
                Sf   = s_S0 + j * avg;
                cntf = (float)s_k0cnt + j;
            }
        }
        float np2 = threshold - cntf;
        out[0] = fmaxf(Sf, np2) / cntf;
    }

    // ---- restore scratch to zero for the next call ----
    __syncthreads();
    for (int j = 0; j < BPT; j++) {
        int b = b0 + j;
        if (b < NBUCK) { g_hcnt[b] = 0; g_hsum[b] = 0.0f; }
    }
    if (tid == 0) { g_nneg = 0; g_tot = 0.0f; g_ticket = 0; }
}

// ---------------------------------------------------------------------------
extern "C" void kernel_launch(void* const* d_in, const int* in_sizes, int n_in,
                              void* d_out, int out_size)
{
    const float* logits = (const float*)d_in[0];
    const int*   target = (const int*)d_in[1];
    const int B = in_sizes[1];
    const int C = in_sizes[0] / B;

    npc_fused_kernel<<<B, NT>>>(logits, target, (float*)d_out, C, B);
}

// round 8
// speedup vs baseline: 1.0525x; 1.0121x over previous
#include <cuda_runtime.h>
#include <math.h>

#define MAX_B    8192
#define NBUCK    4096
#define BSCALE   128.0f       // bucket = int(loss * 128), covers [0, 32)
#define LIST_CAP 1024
#define SORT_CAP 128
#define NT       320
#define BPT      13           // ceil(NBUCK / NT)

__device__ float g_loss[MAX_B];
__device__ int   g_hcnt[NBUCK];    // zero-invariant across calls
__device__ float g_hsum[NBUCK];    // zero-invariant across calls
__device__ int   g_nneg;           // zero-invariant across calls
__device__ float g_tot;            // zero-invariant across calls
__device__ int   g_ticket;         // zero-invariant across calls

// ---------------------------------------------------------------------------
// Single fused kernel. 48-reg cap (4 blocks/SM) leaves room for an explicit
// 5x float4 staged load batch -> MLP_p1 = 5 in the main loop.
//   Phase A (all blocks): per-row top-2 + sum(exp(x)); epilogue deposits
//     loss/hist/nneg/total via spread atomics, threadfence + ticket.
//   Phase B (chip-wide last block): register-light histogram prefix scan,
//     exact boundary walk on the crossing bucket, scalar out, scratch zero.
// ---------------------------------------------------------------------------
__global__ void __launch_bounds__(NT, 4) npc_fused_kernel(
    const float* __restrict__ logits,
    const int*   __restrict__ target,
    float* __restrict__ out,
    int C, int B)
{
    const int row = blockIdx.x;
    const float* __restrict__ p = logits + (long long)row * (long long)C;
    const int tid  = threadIdx.x;
    const int warp = tid >> 5;
    const int lane = tid & 31;

    // ===================== Phase A: per-row pass =====================
    float m1 = -INFINITY;
    float m2 = -INFINITY;
    float s0 = 0.0f, s1 = 0.0f;      // split exp-sum chains

    const int C4 = C >> 2;
    const float4* __restrict__ p4 = (const float4*)p;

    if (C4 == 25 * NT) {
        // fast path: 25 float4 per thread, batched 5 at a time (MLP_p1 = 5)
#pragma unroll
        for (int it = 0; it < 5; it++) {
            float4 r[5];
#pragma unroll
            for (int e = 0; e < 5; e++)
                r[e] = p4[tid + (it * 5 + e) * NT];
#pragma unroll
            for (int e = 0; e < 5; e++) {
                float xs[4] = {r[e].x, r[e].y, r[e].z, r[e].w};
#pragma unroll
                for (int q = 0; q < 4; q++) {
                    float x  = xs[q];
                    float hi = fmaxf(m1, x);
                    float lo = fminf(m1, x);
                    m2 = fmaxf(m2, lo);
                    m1 = hi;
                    if (q & 1) s1 += __expf(x);
                    else       s0 += __expf(x);
                }
            }
        }
    } else {
        // generic path
        for (int i = tid; i < C4; i += NT) {
            float4 v = p4[i];
            float xs[4] = {v.x, v.y, v.z, v.w};
#pragma unroll
            for (int q = 0; q < 4; q++) {
                float x  = xs[q];
                float hi = fmaxf(m1, x);
                float lo = fminf(m1, x);
                m2 = fmaxf(m2, lo);
                m1 = hi;
                if (q & 1) s1 += __expf(x);
                else       s0 += __expf(x);
            }
        }
        for (int i = (C4 << 2) + tid; i < C; i += NT) {
            float x  = p[i];
            float hi = fmaxf(m1, x);
            float lo = fminf(m1, x);
            m2 = fmaxf(m2, lo);
            m1 = hi;
            s0 += __expf(x);
        }
    }
    float s = s0 + s1;

#pragma unroll
    for (int o = 16; o > 0; o >>= 1) {
        float om1 = __shfl_xor_sync(0xffffffffu, m1, o);
        float om2 = __shfl_xor_sync(0xffffffffu, m2, o);
        float os  = __shfl_xor_sync(0xffffffffu, s,  o);
        float lo  = fminf(m1, om1);
        m1 = fmaxf(m1, om1);
        m2 = fmaxf(lo, fmaxf(m2, om2));
        s += os;
    }

    __shared__ float sm1[10], sm2[10], ss[10];
    __shared__ int   s_last;
    if (lane == 0) { sm1[warp] = m1; sm2[warp] = m2; ss[warp] = s; }
    __syncthreads();

    if (tid == 0) {
        float M1 = sm1[0], M2 = sm2[0], S = ss[0];
        for (int w = 1; w < (NT >> 5); w++) {
            float om1 = sm1[w];
            float lo  = fminf(M1, om1);
            M1 = fmaxf(M1, om1);
            M2 = fmaxf(lo, fmaxf(M2, sm2[w]));
            S += ss[w];
        }
        float tgt = p[target[row]];
        float lse = __logf(S);

        float margin1 = tgt - M1;
        float margin  = (margin1 != 0.0f) ? margin1 : (tgt - M2);
        float lv = (margin >= 0.0f) ? fmaxf(1.0f - margin, 0.0f)
                                    : fmaxf(1.0f - tgt + lse, 0.0f);
        g_loss[row] = lv;

        int b = (int)(lv * BSCALE);
        b = max(0, min(NBUCK - 1, b));
        atomicAdd(&g_hcnt[b], 1);
        atomicAdd(&g_hsum[b], lv);
        if (margin < 0.0f) atomicAdd(&g_nneg, 1);
        atomicAdd(&g_tot, lv);

        __threadfence();
        int t = atomicAdd(&g_ticket, 1);
        s_last = (t == gridDim.x - 1) ? 1 : 0;
    }
    __syncthreads();
    if (!s_last) return;

    // ============ Phase B: last block runs the finalize ============
    __threadfence();   // acquire side of the ticket handshake

    __shared__ int   wtc[10];
    __shared__ float wts[10];
    __shared__ float list[LIST_CAP];
    __shared__ int   s_bstar, s_k0cnt, s_cntb, s_ln;
    __shared__ float s_S0, s_sumb;

    if (tid == 0) { s_bstar = -1; s_ln = 0; }

    const int   nneg      = g_nneg;
    const float total_sum = g_tot;
    const float threshold = 0.81f * (float)B + 0.9f * (float)nneg;
    const float T2        = threshold + 2.0f;
    const bool  all_sel   = ((float)B + total_sum <= T2);

    // ---- pass 1: per-thread bucket totals ----
    const int b0 = tid * BPT;
    int   ci = 0;
    float si = 0.0f;
    for (int j = 0; j < BPT; j++) {
        int b = b0 + j;
        if (b < NBUCK) { ci += g_hcnt[b]; si += g_hsum[b]; }
    }

    // ---- hierarchical exclusive pair-scan over thread totals ----
    int   wc = ci;
    float ws = si;
#pragma unroll
    for (int o = 1; o < 32; o <<= 1) {
        int   tc = __shfl_up_sync(0xffffffffu, wc, o);
        float ts = __shfl_up_sync(0xffffffffu, ws, o);
        if (lane >= o) { wc += tc; ws += ts; }
    }
    if (lane == 31) { wtc[warp] = wc; wts[warp] = ws; }
    __syncthreads();
    if (warp == 0) {
        int   tc = (lane < 10) ? wtc[lane] : 0;
        float ts = (lane < 10) ? wts[lane] : 0.0f;
        int   c2 = tc;
        float s2 = ts;
#pragma unroll
        for (int o = 1; o < 32; o <<= 1) {
            int   uc = __shfl_up_sync(0xffffffffu, c2, o);
            float us = __shfl_up_sync(0xffffffffu, s2, o);
            if (lane >= o) { c2 += uc; s2 += us; }
        }
        if (lane < 10) { wtc[lane] = c2 - tc; wts[lane] = s2 - ts; }
    }
    __syncthreads();
    int   K = wtc[warp] + (wc - ci);
    float S = wts[warp] + (ws - si);

    // ---- pass 2: re-read buckets from L2, locate crossing bucket ----
    if (!all_sel) {
        for (int j = 0; j < BPT; j++) {
            int b = b0 + j;
            if (b < NBUCK) {
                int   c = g_hcnt[b];
                float f = g_hsum[b];
                float before = (float)K + S;
                float after  = (float)(K + c) + (S + f);
                if (before <= T2 && after > T2) {
                    s_bstar = b;
                    s_k0cnt = K;
                    s_S0    = S;
                    s_cntb  = c;
                    s_sumb  = f;
                }
                K += c;
                S += f;
            }
        }
    }
    __syncthreads();

    // ---- gather crossing bucket members from g_loss (L2-hot) ----
    const int bstar = s_bstar;
    if (bstar >= 0) {
        for (int i = tid; i < B; i += NT) {
            float L = g_loss[i];
            int b = (int)(L * BSCALE);
            b = max(0, min(NBUCK - 1, b));
            if (b == bstar) {
                int idx = atomicAdd(&s_ln, 1);
                if (idx < LIST_CAP) list[idx] = L;
            }
        }
    }
    __syncthreads();

    // ---- exact boundary walk (thread 0) ----
    if (tid == 0) {
        float Sf, cntf;
        if (all_sel || bstar < 0) {
            Sf = total_sum; cntf = (float)B;
        } else {
            int n = s_ln;
            if (n <= SORT_CAP && n <= LIST_CAP) {
                for (int a = 1; a < n; a++) {           // insertion sort asc
                    float x = list[a];
                    int bp = a - 1;
                    while (bp >= 0 && list[bp] > x) { list[bp + 1] = list[bp]; bp--; }
                    list[bp + 1] = x;
                }
                int   k  = s_k0cnt;
                float Sa = s_S0;
                for (int t = 0; t < n; t++) {
                    float val = list[t];
                    if (Sa + val + (float)(k + 1) <= T2) { Sa += val; k++; }
                    else break;
                }
                Sf = Sa; cntf = (float)k;
            } else {
                float avg = s_sumb / (float)s_cntb;     // near-equal fallback
                float j = floorf((T2 - s_S0 - (float)s_k0cnt) / (avg + 1.0f));
                j = fmaxf(j, 0.0f);
                j = fminf(j, (float)s_cntb);
                Sf   = s_S0 + j * avg;
                cntf = (float)s_k0cnt + j;
            }
        }
        float np2 = threshold - cntf;
        out[0] = fmaxf(Sf, np2) / cntf;
    }

    // ---- restore scratch to zero for the next call ----
    __syncthreads();
    for (int j = 0; j < BPT; j++) {
        int b = b0 + j;
        if (b < NBUCK) { g_hcnt[b] = 0; g_hsum[b] = 0.0f; }
    }
    if (tid == 0) { g_nneg = 0; g_tot = 0.0f; g_ticket = 0; }
}

// ---------------------------------------------------------------------------
extern "C" void kernel_launch(void* const* d_in, const int* in_sizes, int n_in,
                              void* d_out, int out_size)
{
    const float* logits = (const float*)d_in[0];
    const int*   target = (const int*)d_in[1];
    const int B = in_sizes[1];
    const int C = in_sizes[0] / B;

    npc_fused_kernel<<<B, NT>>>(logits, target, (float*)d_out, C, B);
}